// round 3
// baseline (speedup 1.0000x reference)
#include <cuda_runtime.h>
#include <cuda_bf16.h>
#include <cstdint>

// Problem constants
#define NNODE 20000
#define NEDGE 640000
#define NPAIR (NEDGE / 2)

typedef unsigned long long u64;

// ---- scratch (device globals; no allocation allowed) ----
__device__ float g_fs[NNODE * 32];           // features for TP, scalars
__device__ float g_fv[NNODE * 32 * 3];       // features for TP, vectors [n][u][3]
__device__ float g_ss[NNODE * 32];           // self-connection scalars
__device__ float g_sv[NNODE * 32 * 3];       // self-connection vectors [n][v][3]
__device__ float4 g_acc[NNODE * 64];         // scatter accumulator [n][U] = (vx,vy,vz,s)

// scales
#define INV_MUL   0.17677669529663689f   // 1/sqrt(32)
#define MLP0_SC   0.25f                  // 1/sqrt(16)
#define MLP1_SC   0.125f                 // 1/sqrt(64)
#define WI_SC     0.125f                 // 1/sqrt(64)
#define INV_SQRT3 0.57735026918962576f
#define COS_A     0.92387953251128674f   // cos(pi/8)
#define SIN_A     0.38268343236508978f   // sin(pi/8)
#define FSCALE    0.022097086912079608f  // 1/(sqrt(32)*sqrt(64))

// ---- packed f32x2 helpers (ptxas will NOT auto-fuse these; must be PTX) ----
__device__ __forceinline__ u64 pack2(float x, float y) {
    u64 r; asm("mov.b64 %0, {%1, %2};" : "=l"(r) : "f"(x), "f"(y)); return r;
}
__device__ __forceinline__ float2 unpack2(u64 v) {
    float2 f; asm("mov.b64 {%0, %1}, %2;" : "=f"(f.x), "=f"(f.y) : "l"(v)); return f;
}
__device__ __forceinline__ u64 ffma2(u64 a, u64 b, u64 c) {
    u64 d; asm("fma.rn.f32x2 %0, %1, %2, %3;" : "=l"(d) : "l"(a), "l"(b), "l"(c)); return d;
}
__device__ __forceinline__ u64 fmul2(u64 a, u64 b) {
    u64 d; asm("mul.rn.f32x2 %0, %1, %2;" : "=l"(d) : "l"(a), "l"(b)); return d;
}

__device__ __forceinline__ float gelu_tanh(float x) {
    float x3  = x * x * x;
    float arg = 0.7978845608028654f * fmaf(0.044715f, x3, x);
    float t;
    asm("tanh.approx.f32 %0, %1;" : "=f"(t) : "f"(arg));
    return 0.5f * x * (1.0f + t);
}

__device__ __forceinline__ void red_add_v4(float* p, float a, float b, float c, float d) {
    asm volatile("red.global.add.v4.f32 [%0], {%1, %2, %3, %4};"
                 :: "l"(p), "f"(a), "f"(b), "f"(c), "f"(d) : "memory");
}

// ---------------------------------------------------------------------------
// Kernel 0: zero the scatter accumulator
// ---------------------------------------------------------------------------
__global__ void zero_acc_kernel() {
    int idx = blockIdx.x * blockDim.x + threadIdx.x;
    int total = NNODE * 64;
    for (int i = idx; i < total; i += gridDim.x * blockDim.x)
        g_acc[i] = make_float4(0.f, 0.f, 0.f, 0.f);
}

// ---------------------------------------------------------------------------
// Kernel 1: first equivariant linear (features + self-connection)
// ---------------------------------------------------------------------------
__global__ void node_linear_kernel(const float* __restrict__ ns,
                                   const float* __restrict__ nv,
                                   const float* __restrict__ W1s_feat,
                                   const float* __restrict__ W1s_self,
                                   const float* __restrict__ W1v_feat,
                                   const float* __restrict__ W1v_self) {
    int idx = blockIdx.x * blockDim.x + threadIdx.x;
    if (idx >= NNODE * 32) return;
    int n = idx >> 5;
    int v = idx & 31;

    const float* srow = ns + (size_t)n * 32;
    float af = 0.f, as = 0.f;
#pragma unroll
    for (int u = 0; u < 32; u++) {
        float s = srow[u];                         // broadcast within warp
        af = fmaf(s, W1s_feat[u * 32 + v], af);    // coalesced
        as = fmaf(s, W1s_self[u * 32 + v], as);
    }
    g_fs[idx] = af * INV_MUL;
    g_ss[idx] = as * INV_MUL;

    const float* vrow = nv + (size_t)n * 96;
    float f0 = 0.f, f1 = 0.f, f2 = 0.f, s0 = 0.f, s1 = 0.f, s2 = 0.f;
#pragma unroll
    for (int u = 0; u < 32; u++) {
        float wf = W1v_feat[u * 32 + v];
        float ws = W1v_self[u * 32 + v];
        float x = vrow[u * 3 + 0];
        float y = vrow[u * 3 + 1];
        float z = vrow[u * 3 + 2];
        f0 = fmaf(x, wf, f0); f1 = fmaf(y, wf, f1); f2 = fmaf(z, wf, f2);
        s0 = fmaf(x, ws, s0); s1 = fmaf(y, ws, s1); s2 = fmaf(z, ws, s2);
    }
    g_fv[idx * 3 + 0] = f0 * INV_MUL;
    g_fv[idx * 3 + 1] = f1 * INV_MUL;
    g_fv[idx * 3 + 2] = f2 * INV_MUL;
    g_sv[idx * 3 + 0] = s0 * INV_MUL;
    g_sv[idx * 3 + 1] = s1 * INV_MUL;
    g_sv[idx * 3 + 2] = s2 * INV_MUL;
}

// ---------------------------------------------------------------------------
// Kernel 2: per-edge radial MLP + weighted uvu TP + scatter-add
//   TWO edges per thread: every warp-uniform shared weight load (broadcast)
//   feeds both edges' FMAs -> LDS per edge halved; packed f32x2 FMA throughout.
// ---------------------------------------------------------------------------
// shared layout (floats):
//   sW0t [64][16]         : Wmlp0 transposed                     (1024)
//   sW1  [64][64]         : Wmlp1 as-is                          (4096)
//   sWi  [32][4][64]      : Wi0..Wi3, [u][instr][k] k-contiguous (8192)
#define SMEM_FLOATS (1024 + 4096 + 8192)

__global__ __launch_bounds__(128, 2)
void edge_kernel(const float* __restrict__ eas_in,
                 const float* __restrict__ eav,
                 const float* __restrict__ esa,
                 const int*   __restrict__ esrc,
                 const int*   __restrict__ edst,
                 const float* __restrict__ Wmlp0,
                 const float* __restrict__ Wmlp1,
                 const float* __restrict__ Wi0,
                 const float* __restrict__ Wi1,
                 const float* __restrict__ Wi2,
                 const float* __restrict__ Wi3) {
    extern __shared__ float smem[];
    float* sW0t = smem;            // 64*16
    float* sW1  = smem + 1024;     // 64*64
    float* sWi  = smem + 5120;     // 32*4*64

    // stage weights
    for (int i = threadIdx.x; i < 1024; i += blockDim.x) {
        int j = i >> 4, k = i & 15;
        sW0t[i] = Wmlp0[k * 64 + j];
    }
    for (int i = threadIdx.x; i < 4096; i += blockDim.x)
        sW1[i] = Wmlp1[i];
    for (int i = threadIdx.x; i < 2048; i += blockDim.x) {
        int u = i >> 6, k = i & 63;
        sWi[u * 256 +   0 + k] = Wi0[k * 32 + u];
        sWi[u * 256 +  64 + k] = Wi1[k * 32 + u];
        sWi[u * 256 + 128 + k] = Wi2[k * 32 + u];
        sWi[u * 256 + 192 + k] = Wi3[k * 32 + u];
    }
    __syncthreads();

    int p = blockIdx.x * blockDim.x + threadIdx.x;
    if (p >= NPAIR) return;
    int e0 = p;
    int e1 = p + NPAIR;

    // radial embeddings for both edges, packed into f32x2
    u64 xA[8], xB[8];
    {
        const float4* q0 = reinterpret_cast<const float4*>(esa + (size_t)e0 * 16);
        const float4* q1 = reinterpret_cast<const float4*>(esa + (size_t)e1 * 16);
#pragma unroll
        for (int i = 0; i < 4; i++) {
            float4 a = q0[i];
            xA[2 * i]     = pack2(a.x, a.y);
            xA[2 * i + 1] = pack2(a.z, a.w);
            float4 b = q1[i];
            xB[2 * i]     = pack2(b.x, b.y);
            xB[2 * i + 1] = pack2(b.z, b.w);
        }
    }

    // MLP: h kept packed in k-pairs (32 u64 per edge); h0[k] computed on the fly
    u64 hA[32], hB[32];
#pragma unroll
    for (int j = 0; j < 32; j++) { hA[j] = 0ull; hB[j] = 0ull; }

#pragma unroll 1
    for (int k = 0; k < 64; k++) {
        const ulonglong2* w0 = reinterpret_cast<const ulonglong2*>(sW0t + k * 16);
        ulonglong2 wA = w0[0], wB = w0[1], wC = w0[2], wD = w0[3];

        u64 ac0 = fmul2(xA[0], wA.x);
        u64 ac1 = fmul2(xA[1], wA.y);
        u64 bc0 = fmul2(xB[0], wA.x);
        u64 bc1 = fmul2(xB[1], wA.y);
        ac0 = ffma2(xA[2], wB.x, ac0);  bc0 = ffma2(xB[2], wB.x, bc0);
        ac1 = ffma2(xA[3], wB.y, ac1);  bc1 = ffma2(xB[3], wB.y, bc1);
        ac0 = ffma2(xA[4], wC.x, ac0);  bc0 = ffma2(xB[4], wC.x, bc0);
        ac1 = ffma2(xA[5], wC.y, ac1);  bc1 = ffma2(xB[5], wC.y, bc1);
        ac0 = ffma2(xA[6], wD.x, ac0);  bc0 = ffma2(xB[6], wD.x, bc0);
        ac1 = ffma2(xA[7], wD.y, ac1);  bc1 = ffma2(xB[7], wD.y, bc1);

        float2 sa0 = unpack2(ac0), sa1 = unpack2(ac1);
        float2 sb0 = unpack2(bc0), sb1 = unpack2(bc1);
        float h0a = gelu_tanh(((sa0.x + sa0.y) + (sa1.x + sa1.y)) * MLP0_SC);
        float h0b = gelu_tanh(((sb0.x + sb0.y) + (sb1.x + sb1.y)) * MLP0_SC);
        u64 pa = pack2(h0a, h0a);
        u64 pb = pack2(h0b, h0b);

        const ulonglong2* wr = reinterpret_cast<const ulonglong2*>(sW1 + k * 64);
#pragma unroll
        for (int j = 0; j < 16; j++) {
            ulonglong2 w = wr[j];
            hA[2 * j]     = ffma2(pa, w.x, hA[2 * j]);
            hB[2 * j]     = ffma2(pb, w.x, hB[2 * j]);
            hA[2 * j + 1] = ffma2(pa, w.y, hA[2 * j + 1]);
            hB[2 * j + 1] = ffma2(pb, w.y, hB[2 * j + 1]);
        }
    }
    // gelu on packed h
#pragma unroll
    for (int j = 0; j < 32; j++) {
        float2 va = unpack2(hA[j]);
        va.x = gelu_tanh(va.x * MLP1_SC);
        va.y = gelu_tanh(va.y * MLP1_SC);
        hA[j] = pack2(va.x, va.y);
        float2 vb = unpack2(hB[j]);
        vb.x = gelu_tanh(vb.x * MLP1_SC);
        vb.y = gelu_tanh(vb.y * MLP1_SC);
        hB[j] = pack2(vb.x, vb.y);
    }

    // edge data
    int   src0 = esrc[e0],  src1 = esrc[e1];
    int   dst0 = edst[e0],  dst1 = edst[e1];
    float eas0 = eas_in[e0], eas1 = eas_in[e1];
    float av00 = eav[(size_t)e0 * 3 + 0];
    float av01 = eav[(size_t)e0 * 3 + 1];
    float av02 = eav[(size_t)e0 * 3 + 2];
    float av10 = eav[(size_t)e1 * 3 + 0];
    float av11 = eav[(size_t)e1 * 3 + 1];
    float av12 = eav[(size_t)e1 * 3 + 2];

    const float* fs0 = g_fs + (size_t)src0 * 32;
    const float* fv0 = g_fv + (size_t)src0 * 96;
    const float* fs1 = g_fs + (size_t)src1 * 32;
    const float* fv1 = g_fv + (size_t)src1 * 96;
    float* acc0 = reinterpret_cast<float*>(g_acc + (size_t)dst0 * 64);
    float* acc1 = reinterpret_cast<float*>(g_acc + (size_t)dst1 * 64);

#pragma unroll 1
    for (int u = 0; u < 32; u++) {
        const ulonglong2* q = reinterpret_cast<const ulonglong2*>(sWi + (size_t)u * 256);
        // q[0..15]=Wi0 k-pairs, q[16..31]=Wi1, q[32..47]=Wi2, q[48..63]=Wi3
        u64 a0 = 0ull, a1 = 0ull, a2 = 0ull, a3 = 0ull;   // edge0 heads
        u64 b0 = 0ull, b1 = 0ull, b2 = 0ull, b3 = 0ull;   // edge1 heads
#pragma unroll
        for (int j = 0; j < 16; j++) {
            u64 ha0 = hA[2 * j], ha1 = hA[2 * j + 1];
            u64 hb0 = hB[2 * j], hb1 = hB[2 * j + 1];
            ulonglong2 v0 = q[j];
            ulonglong2 v1 = q[16 + j];
            ulonglong2 v2 = q[32 + j];
            ulonglong2 v3 = q[48 + j];
            a0 = ffma2(ha0, v0.x, a0);  b0 = ffma2(hb0, v0.x, b0);
            a1 = ffma2(ha0, v1.x, a1);  b1 = ffma2(hb0, v1.x, b1);
            a2 = ffma2(ha0, v2.x, a2);  b2 = ffma2(hb0, v2.x, b2);
            a3 = ffma2(ha0, v3.x, a3);  b3 = ffma2(hb0, v3.x, b3);
            a0 = ffma2(ha1, v0.y, a0);  b0 = ffma2(hb1, v0.y, b0);
            a1 = ffma2(ha1, v1.y, a1);  b1 = ffma2(hb1, v1.y, b1);
            a2 = ffma2(ha1, v2.y, a2);  b2 = ffma2(hb1, v2.y, b2);
            a3 = ffma2(ha1, v3.y, a3);  b3 = ffma2(hb1, v3.y, b3);
        }
        float2 f;
        f = unpack2(a0); float w0a = f.x + f.y;
        f = unpack2(a1); float w1a = f.x + f.y;
        f = unpack2(a2); float w2a = f.x + f.y;
        f = unpack2(a3); float w3a = f.x + f.y;
        f = unpack2(b0); float w0b = f.x + f.y;
        f = unpack2(b1); float w1b = f.x + f.y;
        f = unpack2(b2); float w2b = f.x + f.y;
        f = unpack2(b3); float w3b = f.x + f.y;

        // ---- edge 0 ----
        {
            float w0 = w0a * WI_SC, w1 = w1a * WI_SC, w2 = w2a * WI_SC, w3 = w3a * WI_SC;
            float esu = fs0[u];
            float ev0 = fv0[u * 3 + 0];
            float ev1 = fv0[u * 3 + 1];
            float ev2 = fv0[u * 3 + 2];
            float w1e = w1 * esu;
            float w2e = w2 * eas0;
            float m0  = w0 * esu * eas0;
            float m3  = w3 * (ev0 * av00 + ev1 * av01 + ev2 * av02) * INV_SQRT3;
            red_add_v4(acc0 + u * 4,        w1e * av00, w1e * av01, w1e * av02, m0);
            red_add_v4(acc0 + (32 + u) * 4, w2e * ev0,  w2e * ev1,  w2e * ev2,  m3);
        }
        // ---- edge 1 ----
        {
            float w0 = w0b * WI_SC, w1 = w1b * WI_SC, w2 = w2b * WI_SC, w3 = w3b * WI_SC;
            float esu = fs1[u];
            float ev0 = fv1[u * 3 + 0];
            float ev1 = fv1[u * 3 + 1];
            float ev2 = fv1[u * 3 + 2];
            float w1e = w1 * esu;
            float w2e = w2 * eas1;
            float m0  = w0 * esu * eas1;
            float m3  = w3 * (ev0 * av10 + ev1 * av11 + ev2 * av12) * INV_SQRT3;
            red_add_v4(acc1 + u * 4,        w1e * av10, w1e * av11, w1e * av12, m0);
            red_add_v4(acc1 + (32 + u) * 4, w2e * ev0,  w2e * ev1,  w2e * ev2,  m3);
        }
    }
}

// ---------------------------------------------------------------------------
// Kernel 3: second equivariant linear + self-connection mix -> d_out
// ---------------------------------------------------------------------------
__global__ void final_kernel(const float* __restrict__ W2s,
                             const float* __restrict__ W2v,
                             float* __restrict__ out) {
    int idx = blockIdx.x * blockDim.x + threadIdx.x;
    if (idx >= NNODE * 32) return;
    int n = idx >> 5;
    int v = idx & 31;

    const float4* arow = g_acc + (size_t)n * 64;
    float cs = 0.f, c0 = 0.f, c1 = 0.f, c2 = 0.f;
#pragma unroll 8
    for (int U = 0; U < 64; U++) {
        float4 a = arow[U];                    // broadcast within warp
        float ws = W2s[U * 32 + v];            // coalesced
        float wv = W2v[U * 32 + v];
        cs = fmaf(a.w, ws, cs);
        c0 = fmaf(a.x, wv, c0);
        c1 = fmaf(a.y, wv, c1);
        c2 = fmaf(a.z, wv, c2);
    }
    const float sf = SIN_A * FSCALE;
    out[idx] = COS_A * g_ss[idx] + sf * cs;
    float* outv = out + NNODE * 32;
    outv[idx * 3 + 0] = COS_A * g_sv[idx * 3 + 0] + sf * c0;
    outv[idx * 3 + 1] = COS_A * g_sv[idx * 3 + 1] + sf * c1;
    outv[idx * 3 + 2] = COS_A * g_sv[idx * 3 + 2] + sf * c2;
}

// ---------------------------------------------------------------------------
extern "C" void kernel_launch(void* const* d_in, const int* in_sizes, int n_in,
                              void* d_out, int out_size) {
    // Disambiguate input ordering at runtime:
    //   dict order:      [..., esa, esrc, edst, W1s_f, ...]  -> in_sizes[5] == 640000
    //   signature order: [..., esa, W1s_f, ..., esrc, edst]  -> in_sizes[5] == 1024
    const float* ns  = (const float*)d_in[0];
    const float* nv  = (const float*)d_in[1];
    const float* eas = (const float*)d_in[2];
    const float* eav = (const float*)d_in[3];
    const float* esa = (const float*)d_in[4];

    const int *esrc, *edst;
    int wb;  // index of W1s_feat
    if (in_sizes[5] == NEDGE) {         // dict order
        esrc = (const int*)d_in[5];
        edst = (const int*)d_in[6];
        wb = 7;
    } else {                            // signature order
        wb = 5;
        esrc = (const int*)d_in[17];
        edst = (const int*)d_in[18];
    }
    const float* W1s_feat = (const float*)d_in[wb + 0];
    const float* W1s_self = (const float*)d_in[wb + 1];
    const float* W1v_feat = (const float*)d_in[wb + 2];
    const float* W1v_self = (const float*)d_in[wb + 3];
    const float* Wmlp0    = (const float*)d_in[wb + 4];
    const float* Wmlp1    = (const float*)d_in[wb + 5];
    const float* Wi0      = (const float*)d_in[wb + 6];
    const float* Wi1      = (const float*)d_in[wb + 7];
    const float* Wi2      = (const float*)d_in[wb + 8];
    const float* Wi3      = (const float*)d_in[wb + 9];
    const float* W2s      = (const float*)d_in[wb + 10];
    const float* W2v      = (const float*)d_in[wb + 11];

    float* out = (float*)d_out;

    // zero accumulator + node linear (independent, both precede edge kernel)
    zero_acc_kernel<<<640, 256>>>();
    node_linear_kernel<<<(NNODE * 32 + 255) / 256, 256>>>(
        ns, nv, W1s_feat, W1s_self, W1v_feat, W1v_self);

    // edge kernel: 53 KB dynamic smem -> raise the limit (idempotent, capture-safe)
    static bool attr_set = false;
    if (!attr_set) {
        cudaFuncSetAttribute(edge_kernel,
                             cudaFuncAttributeMaxDynamicSharedMemorySize,
                             SMEM_FLOATS * (int)sizeof(float));
        attr_set = true;
    }
    edge_kernel<<<(NPAIR + 127) / 128, 128, SMEM_FLOATS * sizeof(float)>>>(
        eas, eav, esa, esrc, edst, Wmlp0, Wmlp1, Wi0, Wi1, Wi2, Wi3);

    final_kernel<<<(NNODE * 32 + 255) / 256, 256>>>(W2s, W2v, out);
}